// round 1
// baseline (speedup 1.0000x reference)
#include <cuda_runtime.h>
#include <math.h>

#define BSZ 16
#define SEQ 2048
#define DKK 64
#define BQ 64
#define BK 64
#define NT 256
#define QS 68            // padded row stride for QsT/KsT/Ps (17*16B -> aligned float4, staggered banks)

// smem layout (floats):
//  QsT [64][68]  (d-major, transposed Q, pre-scaled by 1/8)
//  KsT [64][68]  (d-major, transposed K)
//  Vs  [64][64]  (j-major)
//  Rel [64][128] (d-major window of Krelpos columns)
//  Ps  [64][68]  (softmax probs, row-major)
#define SM_QST 0
#define SM_KST (SM_QST + 64*QS)
#define SM_VS  (SM_KST + 64*QS)
#define SM_REL (SM_VS  + 64*64)
#define SM_PS  (SM_REL + 64*128)
#define SM_FLOATS (SM_PS + 64*QS)
#define SMEM_BYTES (SM_FLOATS * 4)

__global__ __launch_bounds__(NT, 2)
void attn_relpos_kernel(const float* __restrict__ Q, const float* __restrict__ K,
                        const float* __restrict__ V, const float* __restrict__ R,
                        float* __restrict__ O)
{
    extern __shared__ float smem[];
    float* QsT = smem + SM_QST;
    float* KsT = smem + SM_KST;
    float* Vs  = smem + SM_VS;
    float* Rel = smem + SM_REL;
    float* Ps  = smem + SM_PS;

    const int tid = threadIdx.x;
    const int tx = tid & 15;      // col group (4 cols each)
    const int ty = tid >> 4;      // row group (4 rows each)

    // reversed tile order: heavy (long causal loop) CTAs launch first
    const int bq = (int)gridDim.x - 1 - (int)blockIdx.x;
    const int i0 = bq * BQ;
    const int b  = blockIdx.y;

    const float* Qb = Q + ((size_t)b * SEQ + i0) * DKK;

    // ---- load Q tile, transposed + pre-scaled by 1/sqrt(64) ----
    #pragma unroll
    for (int idx = tid; idx < BQ * DKK; idx += NT) {
        int i = idx >> 6, d = idx & 63;
        QsT[d * QS + i] = Qb[idx] * 0.125f;
    }

    float accO[16];
    #pragma unroll
    for (int x = 0; x < 16; ++x) accO[x] = 0.f;
    float m_i[4], l_i[4];
    #pragma unroll
    for (int x = 0; x < 4; ++x) { m_i[x] = -INFINITY; l_i[x] = 0.f; }

    const int relbase = 63 + 4 * (tx - ty);   // in [3,123]; relbase-3 is 16B aligned

    const int nkv = bq + 1;
    for (int t = 0; t < nkv; ++t) {
        const int j0 = t * BK;
        __syncthreads();   // protect KsT/Vs/Rel/Ps from previous iteration's readers

        // ---- load K (transposed), V, Rel window ----
        const float* Kb = K + ((size_t)b * SEQ + j0) * DKK;
        const float* Vb = V + ((size_t)b * SEQ + j0) * DKK;
        #pragma unroll
        for (int idx = tid; idx < BK * DKK; idx += NT) {
            int j = idx >> 6, d = idx & 63;
            KsT[d * QS + j] = Kb[idx];
            Vs[idx] = Vb[idx];
        }
        const int cbase = SEQ - 64 - i0 + j0;   // >= 0 always
        #pragma unroll
        for (int idx = tid; idx < 64 * 128; idx += NT) {
            int d = idx >> 7, u = idx & 127;
            int c = cbase + u;
            Rel[d * 128 + u] = (c < SEQ) ? R[(size_t)d * SEQ + c] : 0.f;
        }
        __syncthreads();

        // ---- score tile: S[i,j] = Q[i]. (K[j] + Krel[:, shift]) ----
        float acc[16];
        #pragma unroll
        for (int x = 0; x < 16; ++x) acc[x] = 0.f;

        #pragma unroll 4
        for (int d = 0; d < DKK; ++d) {
            const float4 q4 = *(const float4*)(QsT + d * QS + ty * 4);
            const float4 k4 = *(const float4*)(KsT + d * QS + tx * 4);
            const float4 ra = *(const float4*)(Rel + d * 128 + relbase - 3);
            const float4 rc = *(const float4*)(Rel + d * 128 + relbase + 1);
            float qv[4] = {q4.x, q4.y, q4.z, q4.w};
            float kv[4] = {k4.x, k4.y, k4.z, k4.w};
            float rv[8] = {ra.x, ra.y, ra.z, ra.w, rc.x, rc.y, rc.z, rc.w};
            #pragma unroll
            for (int ii = 0; ii < 4; ++ii)
                #pragma unroll
                for (int jj = 0; jj < 4; ++jj)
                    acc[ii * 4 + jj] = fmaf(qv[ii], kv[jj] + rv[3 + jj - ii], acc[ii * 4 + jj]);
        }

        // ---- causal mask on diagonal tile ----
        if (j0 == i0) {
            #pragma unroll
            for (int ii = 0; ii < 4; ++ii)
                #pragma unroll
                for (int jj = 0; jj < 4; ++jj)
                    if (tx * 4 + jj > ty * 4 + ii) acc[ii * 4 + jj] = -INFINITY;
        }

        // ---- online softmax (rowwise over 16 lanes sharing ty) ----
        #pragma unroll
        for (int ii = 0; ii < 4; ++ii) {
            float mx = fmaxf(fmaxf(acc[ii*4], acc[ii*4+1]), fmaxf(acc[ii*4+2], acc[ii*4+3]));
            #pragma unroll
            for (int off = 8; off; off >>= 1)
                mx = fmaxf(mx, __shfl_xor_sync(0xffffffffu, mx, off, 16));
            const float mnew = fmaxf(m_i[ii], mx);
            const float corr = __expf(m_i[ii] - mnew);
            m_i[ii] = mnew;
            float ps = 0.f;
            #pragma unroll
            for (int jj = 0; jj < 4; ++jj) {
                float p = __expf(acc[ii*4+jj] - mnew);
                acc[ii*4+jj] = p;
                ps += p;
            }
            #pragma unroll
            for (int off = 8; off; off >>= 1)
                ps += __shfl_xor_sync(0xffffffffu, ps, off, 16);
            l_i[ii] = l_i[ii] * corr + ps;
            #pragma unroll
            for (int jj = 0; jj < 4; ++jj) accO[ii*4+jj] *= corr;
        }

        // ---- stage P to smem ----
        #pragma unroll
        for (int ii = 0; ii < 4; ++ii)
            *(float4*)(Ps + (ty * 4 + ii) * QS + tx * 4) =
                make_float4(acc[ii*4], acc[ii*4+1], acc[ii*4+2], acc[ii*4+3]);
        __syncthreads();

        // ---- O += P @ V ----
        #pragma unroll 2
        for (int j = 0; j < BK; j += 4) {
            float4 p4[4];
            #pragma unroll
            for (int ii = 0; ii < 4; ++ii)
                p4[ii] = *(const float4*)(Ps + (ty * 4 + ii) * QS + j);
            #pragma unroll
            for (int u = 0; u < 4; ++u) {
                const float4 v4 = *(const float4*)(Vs + (j + u) * 64 + tx * 4);
                #pragma unroll
                for (int ii = 0; ii < 4; ++ii) {
                    const float pv = ((const float*)&p4[ii])[u];
                    accO[ii*4+0] = fmaf(pv, v4.x, accO[ii*4+0]);
                    accO[ii*4+1] = fmaf(pv, v4.y, accO[ii*4+1]);
                    accO[ii*4+2] = fmaf(pv, v4.z, accO[ii*4+2]);
                    accO[ii*4+3] = fmaf(pv, v4.w, accO[ii*4+3]);
                }
            }
        }
    }

    // ---- epilogue: normalize + store ----
    float* Ob = O + ((size_t)b * SEQ + i0) * DKK;
    #pragma unroll
    for (int ii = 0; ii < 4; ++ii) {
        const float inv = 1.0f / l_i[ii];
        const int row = ty * 4 + ii;
        *(float4*)(Ob + row * DKK + tx * 4) =
            make_float4(accO[ii*4+0]*inv, accO[ii*4+1]*inv, accO[ii*4+2]*inv, accO[ii*4+3]*inv);
    }
}

extern "C" void kernel_launch(void* const* d_in, const int* in_sizes, int n_in,
                              void* d_out, int out_size)
{
    const float* Q = (const float*)d_in[0];
    const float* K = (const float*)d_in[1];
    const float* V = (const float*)d_in[2];
    const float* R = (const float*)d_in[3];   // Krelpos [64, 2048]
    float* O = (float*)d_out;

    cudaFuncSetAttribute(attn_relpos_kernel,
                         cudaFuncAttributeMaxDynamicSharedMemorySize, SMEM_BYTES);
    dim3 grid(SEQ / BQ, BSZ);   // 32 x 16
    attn_relpos_kernel<<<grid, NT, SMEM_BYTES>>>(Q, K, V, R, O);
}